// round 2
// baseline (speedup 1.0000x reference)
#include <cuda_runtime.h>
#include <cuda_bf16.h>

// ---------------------------------------------------------------------------
// LJ 12-6 over a neighbor list. Round 2: MLP + helper-kernel vectorization.
//   - Pair kernel: 8 pairs/thread, all 16 float4 gathers batched before any
//     branching so ptxas front-loads the LDG.128s (hides L2 ~250cyc latency).
//   - Only ~2% of pairs pass the cutoff mask -> atomics are negligible.
//   - pack/writeout: 4 atoms/thread, 128-bit ld/st everywhere.
// ---------------------------------------------------------------------------

#define MAX_ATOMS 200000

__device__ float4 g_acc[MAX_ATOMS];   // {E, fx, fy, fz}
__device__ float4 g_R4[MAX_ATOMS];    // packed positions, w unused

// Kernel 1: pack R (AoS f32x3) into float4 + zero accumulators. 4 atoms/thread.
__global__ void pack_zero_kernel(const float* __restrict__ R, int n_atoms) {
    int t = blockIdx.x * blockDim.x + threadIdx.x;
    int a = t * 4;
    if (a + 3 < n_atoms) {
        const float4* R4 = reinterpret_cast<const float4*>(R);
        float4 v0 = __ldg(R4 + t * 3 + 0);   // x0 y0 z0 x1
        float4 v1 = __ldg(R4 + t * 3 + 1);   // y1 z1 x2 y2
        float4 v2 = __ldg(R4 + t * 3 + 2);   // z2 x3 y3 z3
        g_R4[a + 0] = make_float4(v0.x, v0.y, v0.z, 0.0f);
        g_R4[a + 1] = make_float4(v0.w, v1.x, v1.y, 0.0f);
        g_R4[a + 2] = make_float4(v1.z, v1.w, v2.x, 0.0f);
        g_R4[a + 3] = make_float4(v2.y, v2.z, v2.w, 0.0f);
        float4 z = make_float4(0.0f, 0.0f, 0.0f, 0.0f);
        g_acc[a + 0] = z; g_acc[a + 1] = z; g_acc[a + 2] = z; g_acc[a + 3] = z;
    } else {
        for (int k = 0; k < 4; k++) {
            int aa = a + k;
            if (aa < n_atoms) {
                g_R4[aa] = make_float4(R[3 * aa], R[3 * aa + 1], R[3 * aa + 2], 0.0f);
                g_acc[aa] = make_float4(0.0f, 0.0f, 0.0f, 0.0f);
            }
        }
    }
}

// Kernel 2: pair loop, 8 pairs per thread.
#define PPT 8
__global__ __launch_bounds__(256) void lj_pairs_kernel(
        const int* __restrict__ idx_i,
        const int* __restrict__ idx_j,
        const float* __restrict__ p_eps,
        const float* __restrict__ p_sig,
        const float* __restrict__ p_cut,
        int n_pairs) {
    const float eps  = __ldg(p_eps);
    const float sig  = __ldg(p_sig);
    const float cut2 = __ldg(p_cut) * __ldg(p_cut);
    const float sig2 = sig * sig;

    long long t    = blockIdx.x * (long long)blockDim.x + threadIdx.x;
    long long base = t * PPT;
    if (base >= n_pairs) return;

    if (base + PPT - 1 < n_pairs) {
        // ---- fast path: fully batched, branch-free load phase ----
        const int4* vi4 = reinterpret_cast<const int4*>(idx_i) + t * 2;
        const int4* vj4 = reinterpret_cast<const int4*>(idx_j) + t * 2;
        int4 ia = __ldg(vi4 + 0), ib = __ldg(vi4 + 1);
        int4 ja = __ldg(vj4 + 0), jb = __ldg(vj4 + 1);
        int ii[PPT] = {ia.x, ia.y, ia.z, ia.w, ib.x, ib.y, ib.z, ib.w};
        int jj[PPT] = {ja.x, ja.y, ja.z, ja.w, jb.x, jb.y, jb.z, jb.w};

        float dx[PPT], dy[PPT], dz[PPT], r2[PPT];
        #pragma unroll
        for (int k = 0; k < PPT; k++) {
            float4 Ri = __ldg(&g_R4[ii[k]]);
            float4 Rj = __ldg(&g_R4[jj[k]]);
            dx[k] = Ri.x - Rj.x;
            dy[k] = Ri.y - Rj.y;
            dz[k] = Ri.z - Rj.z;
            r2[k] = fmaf(dx[k], dx[k], fmaf(dy[k], dy[k], dz[k] * dz[k]));
        }

        #pragma unroll
        for (int k = 0; k < PPT; k++) {
            if (r2[k] < cut2 && r2[k] > 1e-10f) {
                float inv  = __fdividef(1.0f, r2[k]);
                float sr2  = sig2 * inv;
                float sr6  = sr2 * sr2 * sr2;
                float sr12 = sr6 * sr6;
                float e    = 4.0f * eps * (sr12 - sr6);
                float fm   = 24.0f * eps * fmaf(2.0f, sr12, -sr6) * inv;
                float* acc = reinterpret_cast<float*>(&g_acc[ii[k]]);
                atomicAdd(acc + 0, e);
                atomicAdd(acc + 1, fm * dx[k]);
                atomicAdd(acc + 2, fm * dy[k]);
                atomicAdd(acc + 3, fm * dz[k]);
            }
        }
    } else {
        // ---- tail path: scalar ----
        for (int k = 0; k < PPT; k++) {
            long long p = base + k;
            if (p >= n_pairs) break;
            int i = __ldg(&idx_i[p]);
            int j = __ldg(&idx_j[p]);
            float4 Ri = __ldg(&g_R4[i]);
            float4 Rj = __ldg(&g_R4[j]);
            float ddx = Ri.x - Rj.x, ddy = Ri.y - Rj.y, ddz = Ri.z - Rj.z;
            float rr2 = fmaf(ddx, ddx, fmaf(ddy, ddy, ddz * ddz));
            if (rr2 < cut2 && rr2 > 1e-10f) {
                float inv  = __fdividef(1.0f, rr2);
                float sr2  = sig2 * inv;
                float sr6  = sr2 * sr2 * sr2;
                float sr12 = sr6 * sr6;
                float e    = 4.0f * eps * (sr12 - sr6);
                float fm   = 24.0f * eps * fmaf(2.0f, sr12, -sr6) * inv;
                float* acc = reinterpret_cast<float*>(&g_acc[i]);
                atomicAdd(acc + 0, e);
                atomicAdd(acc + 1, fm * ddx);
                atomicAdd(acc + 2, fm * ddy);
                atomicAdd(acc + 3, fm * ddz);
            }
        }
    }
}

// Kernel 3: reshape accumulators. 4 atoms/thread, 128-bit stores.
__global__ void writeout_kernel(float* __restrict__ out, int n_atoms) {
    int t = blockIdx.x * blockDim.x + threadIdx.x;
    int a = t * 4;
    if (a + 3 < n_atoms) {
        float4 v0 = g_acc[a + 0];
        float4 v1 = g_acc[a + 1];
        float4 v2 = g_acc[a + 2];
        float4 v3 = g_acc[a + 3];
        reinterpret_cast<float4*>(out)[t] =
            make_float4(0.5f * v0.x, 0.5f * v1.x, 0.5f * v2.x, 0.5f * v3.x);
        float4* f = reinterpret_cast<float4*>(out + n_atoms) + t * 3;
        f[0] = make_float4(v0.y, v0.z, v0.w, v1.y);
        f[1] = make_float4(v1.z, v1.w, v2.y, v2.z);
        f[2] = make_float4(v2.w, v3.y, v3.z, v3.w);
    } else {
        for (int k = 0; k < 4; k++) {
            int aa = a + k;
            if (aa < n_atoms) {
                float4 v = g_acc[aa];
                out[aa] = 0.5f * v.x;
                float* f = out + n_atoms;
                f[3 * aa + 0] = v.y;
                f[3 * aa + 1] = v.z;
                f[3 * aa + 2] = v.w;
            }
        }
    }
}

extern "C" void kernel_launch(void* const* d_in, const int* in_sizes, int n_in,
                              void* d_out, int out_size) {
    const float* R     = (const float*)d_in[0];
    const float* eps   = (const float*)d_in[1];
    const float* sig   = (const float*)d_in[2];
    const float* cut   = (const float*)d_in[3];
    const int*   idx_i = (const int*)d_in[4];
    const int*   idx_j = (const int*)d_in[5];
    float*       out   = (float*)d_out;

    int n_atoms = in_sizes[0] / 3;
    int n_pairs = in_sizes[4];

    const int T = 256;
    int atom_groups  = (n_atoms + 3) / 4;
    int blocks_atoms = (atom_groups + T - 1) / T;
    long long pair_groups = ((long long)n_pairs + PPT - 1) / PPT;
    int blocks_pairs = (int)((pair_groups + T - 1) / T);

    pack_zero_kernel<<<blocks_atoms, T>>>(R, n_atoms);
    lj_pairs_kernel<<<blocks_pairs, T>>>(idx_i, idx_j, eps, sig, cut, n_pairs);
    writeout_kernel<<<blocks_atoms, T>>>(out, n_atoms);
}